// round 1
// baseline (speedup 1.0000x reference)
#include <cuda_runtime.h>

#define PI_F 3.14159265358979f

struct Params {
    float c_spec0_x, c_spec0_y, c_spec0_z;     // lerp(spec*0.08*lerp(1,ct,sp_tint), cd_lin, mtl)
    float sheen_x, sheen_y, sheen_z;           // sh*(1-mtl)*lerp(1,ct,sh_tint)
    float diff_x, diff_y, diff_z;              // (1-mtl)/PI * cd_lin
    float sub, rough;
    float ax2, ay2;                            // ax^2, ay^2
    float inv_ax2, inv_ay2;                    // 1/ax^2, 1/ay^2
    float pi_ax_ay;                            // PI*ax*ay
    float a2m1, dr_k;                          // clearcoat: t = 1 + a2m1*cnh^2 ; Dr = dr_k / t
    float cc025;                               // 0.25*clear_coat
};

__device__ Params g_params;

__device__ __forceinline__ float lerpf(float a, float b, float w) { return a + w * (b - a); }

__global__ void setup_kernel(const float* __restrict__ base_color,
                             const float* __restrict__ metallic,
                             const float* __restrict__ subsurface,
                             const float* __restrict__ specular,
                             const float* __restrict__ roughness,
                             const float* __restrict__ specular_tint,
                             const float* __restrict__ anisotropic,
                             const float* __restrict__ sheen,
                             const float* __restrict__ sheen_tint,
                             const float* __restrict__ clear_coat,
                             const float* __restrict__ clear_coat_gloss) {
    float mtl = metallic[0];
    float sub = subsurface[0];
    float spec = specular[0];
    float rough = roughness[0];
    float sp_tint = specular_tint[0];
    float aniso = anisotropic[0];
    float sh = sheen[0];
    float sh_tint = sheen_tint[0];
    float cc = clear_coat[0];
    float ccg = clear_coat_gloss[0];

    float cd[3];
    #pragma unroll
    for (int i = 0; i < 3; i++) cd[i] = powf(base_color[i], 2.2f);
    float lum = 0.3f * cd[0] + 0.6f * cd[1] + 0.1f * cd[2];
    float ct[3];
    #pragma unroll
    for (int i = 0; i < 3; i++)
        ct[i] = (lum > 0.0f) ? cd[i] / fmaxf(lum, 1e-20f) : 0.0f;

    Params p;
    float cs[3], shn[3], df[3];
    #pragma unroll
    for (int i = 0; i < 3; i++) {
        cs[i]  = lerpf(spec * 0.08f * lerpf(1.0f, ct[i], sp_tint), cd[i], mtl);
        shn[i] = sh * (1.0f - mtl) * lerpf(1.0f, ct[i], sh_tint);
        df[i]  = (1.0f - mtl) * (1.0f / PI_F) * cd[i];
    }
    p.c_spec0_x = cs[0]; p.c_spec0_y = cs[1]; p.c_spec0_z = cs[2];
    p.sheen_x = shn[0];  p.sheen_y = shn[1];  p.sheen_z = shn[2];
    p.diff_x = df[0];    p.diff_y = df[1];    p.diff_z = df[2];
    p.sub = sub;
    p.rough = rough;

    float aspect = sqrtf(1.0f - aniso * 0.9f);
    float r2 = rough * rough;
    float ax = fmaxf(0.001f, r2 / aspect);
    float ay = fmaxf(0.001f, r2 * aspect);
    p.ax2 = ax * ax;
    p.ay2 = ay * ay;
    p.inv_ax2 = 1.0f / (ax * ax);
    p.inv_ay2 = 1.0f / (ay * ay);
    p.pi_ax_ay = PI_F * ax * ay;

    float a_cc = lerpf(0.1f, 0.001f, ccg);
    float a2 = a_cc * a_cc;
    if (a_cc >= 1.0f) {
        p.a2m1 = 0.0f;
        p.dr_k = 1.0f / PI_F;
    } else {
        p.a2m1 = a2 - 1.0f;
        p.dr_k = (a2 - 1.0f) / (PI_F * logf(a2));
    }
    p.cc025 = 0.25f * cc;
    g_params = p;
}

// Compute BRDF for one (light, view) pair. Inputs: l[3], v[3]. Writes o[3].
__device__ __forceinline__ void brdf_one(const Params& p,
                                         float lx, float ly, float lz,
                                         float vx, float vy, float vz,
                                         float* o) {
    float hx = lx + vx, hy = ly + vy, hz = lz + vz;
    float inv_h = rsqrtf(hx * hx + hy * hy + hz * hz);
    hx *= inv_h; hy *= inv_h; hz *= inv_h;

    float cos_nl = lz;
    float cos_nv = vz;
    float cnh = hz;
    float chl = hx * lx + hy * ly + hz * lz;

    bool valid = (cos_nl >= 0.0f) && (cos_nv >= 0.0f);
    float cnl = valid ? cos_nl : 0.5f;
    float cnv = valid ? cos_nv : 0.5f;

    // schlick(u) = clamp(1-u,0,1)^5
    float ml = __saturatef(1.0f - cnl);
    float mv = __saturatef(1.0f - cnv);
    float mh = __saturatef(1.0f - chl);
    float ml2 = ml * ml, mv2 = mv * mv, mh2 = mh * mh;
    float fl = ml2 * ml2 * ml;
    float fv = mv2 * mv2 * mv;
    float FH = mh2 * mh2 * mh;

    float c2r = chl * chl * p.rough;
    // fd = lerp(1,fd90,fl)*lerp(1,fd90,fv), fd90 = 0.5 + 2*c2r
    float fd90m1 = 2.0f * c2r - 0.5f;
    float fd = (1.0f + fd90m1 * fl) * (1.0f + fd90m1 * fv);
    // fss with fss90 = c2r
    float fssm1 = c2r - 1.0f;
    float fss = (1.0f + fssm1 * fl) * (1.0f + fssm1 * fv);
    float ss = 1.25f * (fss * (__fdividef(1.0f, cnl + cnv) - 0.5f) + 0.5f);

    // Ds denominator: PI*ax*ay*d^2, d = hx^2/ax^2 + hy^2/ay^2 + cnh^2
    float d = fmaf(hx * hx, p.inv_ax2, fmaf(hy * hy, p.inv_ay2, cnh * cnh));
    float dsden = p.pi_ax_ay * d * d;

    // G terms: As = cnl + sqrt((lx*ax)^2 + (ly*ay)^2 + cnl^2); sqrt via x*rsqrt(x)
    float sa = fmaf(lx * lx, p.ax2, fmaf(ly * ly, p.ay2, cnl * cnl));
    float As = cnl + sa * rsqrtf(sa);
    float sv = fmaf(vx * vx, p.ax2, fmaf(vy * vy, p.ay2, cnv * cnv));
    float Av = cnv + sv * rsqrtf(sv);
    float GsDs = __fdividef(1.0f, dsden * As * Av);

    // clear coat: g025(c) = 1/(c + sqrt(0.0625 + 0.9375*c^2))
    float ga = fmaf(cnl * cnl, 0.9375f, 0.0625f);
    float gb = fmaf(cnv * cnv, 0.9375f, 0.0625f);
    float Br = (cnl + ga * rsqrtf(ga)) * (cnv + gb * rsqrtf(gb));
    float t = fmaf(p.a2m1, cnh * cnh, 1.0f);
    float Fr = fmaf(0.96f, FH, 0.04f);
    float clear = p.cc025 * Fr * p.dr_k * __fdividef(1.0f, t * Br);

    float dm = fd + (ss - fd) * p.sub;

    float rx = p.diff_x * dm + FH * p.sheen_x + GsDs * (p.c_spec0_x + FH * (1.0f - p.c_spec0_x)) + clear;
    float ry = p.diff_y * dm + FH * p.sheen_y + GsDs * (p.c_spec0_y + FH * (1.0f - p.c_spec0_y)) + clear;
    float rz = p.diff_z * dm + FH * p.sheen_z + GsDs * (p.c_spec0_z + FH * (1.0f - p.c_spec0_z)) + clear;

    o[0] = valid ? rx : 0.0f;
    o[1] = valid ? ry : 0.0f;
    o[2] = valid ? rz : 0.0f;
}

// Vectorized: each thread handles 4 elements (24 floats in = 6 float4, 12 out = 3 float4).
__global__ void brdf_kernel_vec(const float4* __restrict__ in,
                                float4* __restrict__ out, int nquad) {
    int tid = blockIdx.x * blockDim.x + threadIdx.x;
    if (tid >= nquad) return;
    Params p = g_params;

    float4 L[6];
    #pragma unroll
    for (int i = 0; i < 6; i++) L[i] = in[(size_t)tid * 6 + i];

    float ibuf[24];
    #pragma unroll
    for (int i = 0; i < 6; i++) {
        ibuf[4 * i + 0] = L[i].x;
        ibuf[4 * i + 1] = L[i].y;
        ibuf[4 * i + 2] = L[i].z;
        ibuf[4 * i + 3] = L[i].w;
    }

    float obuf[12];
    #pragma unroll
    for (int e = 0; e < 4; e++) {
        brdf_one(p,
                 ibuf[6 * e + 0], ibuf[6 * e + 1], ibuf[6 * e + 2],
                 ibuf[6 * e + 3], ibuf[6 * e + 4], ibuf[6 * e + 5],
                 &obuf[3 * e]);
    }

    #pragma unroll
    for (int i = 0; i < 3; i++) {
        float4 o;
        o.x = obuf[4 * i + 0];
        o.y = obuf[4 * i + 1];
        o.z = obuf[4 * i + 2];
        o.w = obuf[4 * i + 3];
        out[(size_t)tid * 3 + i] = o;
    }
}

// Scalar tail kernel (handles elements [start, n))
__global__ void brdf_kernel_tail(const float* __restrict__ in,
                                 float* __restrict__ out, int start, int n) {
    int i = start + blockIdx.x * blockDim.x + threadIdx.x;
    if (i >= n) return;
    Params p = g_params;
    const float* q = in + (size_t)i * 6;
    float o[3];
    brdf_one(p, q[0], q[1], q[2], q[3], q[4], q[5], o);
    out[(size_t)i * 3 + 0] = o[0];
    out[(size_t)i * 3 + 1] = o[1];
    out[(size_t)i * 3 + 2] = o[2];
}

extern "C" void kernel_launch(void* const* d_in, const int* in_sizes, int n_in,
                              void* d_out, int out_size) {
    const float* inputs = (const float*)d_in[0];
    int n = in_sizes[0] / 6;  // N elements, each 2x3 floats

    setup_kernel<<<1, 1>>>(
        (const float*)d_in[1],  (const float*)d_in[2],  (const float*)d_in[3],
        (const float*)d_in[4],  (const float*)d_in[5],  (const float*)d_in[6],
        (const float*)d_in[7],  (const float*)d_in[8],  (const float*)d_in[9],
        (const float*)d_in[10], (const float*)d_in[11]);

    int nquad = n / 4;
    if (nquad > 0) {
        int threads = 256;
        int blocks = (nquad + threads - 1) / threads;
        brdf_kernel_vec<<<blocks, threads>>>((const float4*)inputs,
                                             (float4*)d_out, nquad);
    }
    int rem = n - nquad * 4;
    if (rem > 0) {
        brdf_kernel_tail<<<1, 256>>>(inputs, (float*)d_out, nquad * 4, n);
    }
}

// round 2
// speedup vs baseline: 1.1220x; 1.1220x over previous
#include <cuda_runtime.h>

#define PI_F 3.14159265358979f

struct Params {
    float c_spec0_x, c_spec0_y, c_spec0_z;
    float sheen_x, sheen_y, sheen_z;
    float diff_x, diff_y, diff_z;
    float sub, rough;
    float ax2, ay2;
    float inv_ax2, inv_ay2;
    float pi_ax_ay;
    float a2m1, dr_k;
    float cc025;
};

__device__ __forceinline__ float lerpf(float a, float b, float w) { return a + w * (b - a); }

// Computed by one thread per block; all loads hit L2/L1 after the first block.
__device__ __forceinline__ Params compute_params(
        const float* __restrict__ base_color, const float* __restrict__ metallic,
        const float* __restrict__ subsurface, const float* __restrict__ specular,
        const float* __restrict__ roughness, const float* __restrict__ specular_tint,
        const float* __restrict__ anisotropic, const float* __restrict__ sheen,
        const float* __restrict__ sheen_tint, const float* __restrict__ clear_coat,
        const float* __restrict__ clear_coat_gloss) {
    float mtl = metallic[0];
    float sub = subsurface[0];
    float spec = specular[0];
    float rough = roughness[0];
    float sp_tint = specular_tint[0];
    float aniso = anisotropic[0];
    float sh = sheen[0];
    float sh_tint = sheen_tint[0];
    float cc = clear_coat[0];
    float ccg = clear_coat_gloss[0];

    float cd[3];
    #pragma unroll
    for (int i = 0; i < 3; i++) cd[i] = powf(base_color[i], 2.2f);
    float lum = 0.3f * cd[0] + 0.6f * cd[1] + 0.1f * cd[2];
    float ct[3];
    #pragma unroll
    for (int i = 0; i < 3; i++)
        ct[i] = (lum > 0.0f) ? cd[i] / fmaxf(lum, 1e-20f) : 0.0f;

    Params p;
    float cs[3], shn[3], df[3];
    #pragma unroll
    for (int i = 0; i < 3; i++) {
        cs[i]  = lerpf(spec * 0.08f * lerpf(1.0f, ct[i], sp_tint), cd[i], mtl);
        shn[i] = sh * (1.0f - mtl) * lerpf(1.0f, ct[i], sh_tint);
        df[i]  = (1.0f - mtl) * (1.0f / PI_F) * cd[i];
    }
    p.c_spec0_x = cs[0]; p.c_spec0_y = cs[1]; p.c_spec0_z = cs[2];
    p.sheen_x = shn[0];  p.sheen_y = shn[1];  p.sheen_z = shn[2];
    p.diff_x = df[0];    p.diff_y = df[1];    p.diff_z = df[2];
    p.sub = sub;
    p.rough = rough;

    float aspect = sqrtf(1.0f - aniso * 0.9f);
    float r2 = rough * rough;
    float ax = fmaxf(0.001f, r2 / aspect);
    float ay = fmaxf(0.001f, r2 * aspect);
    p.ax2 = ax * ax;
    p.ay2 = ay * ay;
    p.inv_ax2 = 1.0f / (ax * ax);
    p.inv_ay2 = 1.0f / (ay * ay);
    p.pi_ax_ay = PI_F * ax * ay;

    float a_cc = lerpf(0.1f, 0.001f, ccg);
    float a2 = a_cc * a_cc;
    if (a_cc >= 1.0f) {
        p.a2m1 = 0.0f;
        p.dr_k = 1.0f / PI_F;
    } else {
        p.a2m1 = a2 - 1.0f;
        p.dr_k = (a2 - 1.0f) / (PI_F * logf(a2));
    }
    p.cc025 = 0.25f * cc;
    return p;
}

__device__ __forceinline__ void brdf_one(const Params& p,
                                         float lx, float ly, float lz,
                                         float vx, float vy, float vz,
                                         float* o) {
    float hx = lx + vx, hy = ly + vy, hz = lz + vz;
    float inv_h = rsqrtf(hx * hx + hy * hy + hz * hz);
    hx *= inv_h; hy *= inv_h; hz *= inv_h;

    float cos_nl = lz;
    float cos_nv = vz;
    float cnh = hz;
    float chl = hx * lx + hy * ly + hz * lz;

    bool valid = (cos_nl >= 0.0f) && (cos_nv >= 0.0f);
    float cnl = valid ? cos_nl : 0.5f;
    float cnv = valid ? cos_nv : 0.5f;

    float ml = __saturatef(1.0f - cnl);
    float mv = __saturatef(1.0f - cnv);
    float mh = __saturatef(1.0f - chl);
    float ml2 = ml * ml, mv2 = mv * mv, mh2 = mh * mh;
    float fl = ml2 * ml2 * ml;
    float fv = mv2 * mv2 * mv;
    float FH = mh2 * mh2 * mh;

    float c2r = chl * chl * p.rough;
    float fd90m1 = 2.0f * c2r - 0.5f;
    float fd = (1.0f + fd90m1 * fl) * (1.0f + fd90m1 * fv);
    float fssm1 = c2r - 1.0f;
    float fss = (1.0f + fssm1 * fl) * (1.0f + fssm1 * fv);
    float ss = 1.25f * (fss * (__fdividef(1.0f, cnl + cnv) - 0.5f) + 0.5f);

    float d = fmaf(hx * hx, p.inv_ax2, fmaf(hy * hy, p.inv_ay2, cnh * cnh));
    float dsden = p.pi_ax_ay * d * d;

    float sa = fmaf(lx * lx, p.ax2, fmaf(ly * ly, p.ay2, cnl * cnl));
    float As = cnl + sa * rsqrtf(sa);
    float sv = fmaf(vx * vx, p.ax2, fmaf(vy * vy, p.ay2, cnv * cnv));
    float Av = cnv + sv * rsqrtf(sv);
    float GsDs = __fdividef(1.0f, dsden * As * Av);

    float ga = fmaf(cnl * cnl, 0.9375f, 0.0625f);
    float gb = fmaf(cnv * cnv, 0.9375f, 0.0625f);
    float Br = (cnl + ga * rsqrtf(ga)) * (cnv + gb * rsqrtf(gb));
    float t = fmaf(p.a2m1, cnh * cnh, 1.0f);
    float Fr = fmaf(0.96f, FH, 0.04f);
    float clear = p.cc025 * Fr * p.dr_k * __fdividef(1.0f, t * Br);

    float dm = fd + (ss - fd) * p.sub;

    float rx = p.diff_x * dm + FH * p.sheen_x + GsDs * (p.c_spec0_x + FH * (1.0f - p.c_spec0_x)) + clear;
    float ry = p.diff_y * dm + FH * p.sheen_y + GsDs * (p.c_spec0_y + FH * (1.0f - p.c_spec0_y)) + clear;
    float rz = p.diff_z * dm + FH * p.sheen_z + GsDs * (p.c_spec0_z + FH * (1.0f - p.c_spec0_z)) + clear;

    o[0] = valid ? rx : 0.0f;
    o[1] = valid ? ry : 0.0f;
    o[2] = valid ? rz : 0.0f;
}

#define SCALAR_ARGS                                                            \
    const float* __restrict__ a_bc,  const float* __restrict__ a_mtl,          \
    const float* __restrict__ a_sub, const float* __restrict__ a_spec,         \
    const float* __restrict__ a_rgh, const float* __restrict__ a_spt,          \
    const float* __restrict__ a_ani, const float* __restrict__ a_shn,          \
    const float* __restrict__ a_sht, const float* __restrict__ a_cc,           \
    const float* __restrict__ a_ccg

#define SCALAR_PASS a_bc, a_mtl, a_sub, a_spec, a_rgh, a_spt, a_ani, a_shn, a_sht, a_cc, a_ccg

// Fused: params computed per-block in smem; 4 elements/thread via float4 I/O.
__global__ void __launch_bounds__(128)
brdf_kernel_vec(const float4* __restrict__ in, float4* __restrict__ out,
                int nquad, SCALAR_ARGS) {
    __shared__ Params sp;
    int tid = blockIdx.x * blockDim.x + threadIdx.x;
    bool active = tid < nquad;

    // Issue bulk loads BEFORE the barrier so they overlap param computation.
    float4 L[6];
    if (active) {
        #pragma unroll
        for (int i = 0; i < 6; i++) L[i] = __ldcs(&in[(size_t)tid * 6 + i]);
    }

    if (threadIdx.x == 0) sp = compute_params(SCALAR_PASS);
    __syncthreads();
    if (!active) return;
    Params p = sp;

    float ibuf[24];
    #pragma unroll
    for (int i = 0; i < 6; i++) {
        ibuf[4 * i + 0] = L[i].x;
        ibuf[4 * i + 1] = L[i].y;
        ibuf[4 * i + 2] = L[i].z;
        ibuf[4 * i + 3] = L[i].w;
    }

    float obuf[12];
    #pragma unroll
    for (int e = 0; e < 4; e++) {
        brdf_one(p,
                 ibuf[6 * e + 0], ibuf[6 * e + 1], ibuf[6 * e + 2],
                 ibuf[6 * e + 3], ibuf[6 * e + 4], ibuf[6 * e + 5],
                 &obuf[3 * e]);
    }

    #pragma unroll
    for (int i = 0; i < 3; i++) {
        float4 o;
        o.x = obuf[4 * i + 0];
        o.y = obuf[4 * i + 1];
        o.z = obuf[4 * i + 2];
        o.w = obuf[4 * i + 3];
        __stcs(&out[(size_t)tid * 3 + i], o);
    }
}

// Scalar tail (elements [start, n)); params recomputed per-block.
__global__ void __launch_bounds__(128)
brdf_kernel_tail(const float* __restrict__ in, float* __restrict__ out,
                 int start, int n, SCALAR_ARGS) {
    __shared__ Params sp;
    if (threadIdx.x == 0) sp = compute_params(SCALAR_PASS);
    __syncthreads();
    int i = start + blockIdx.x * blockDim.x + threadIdx.x;
    if (i >= n) return;
    Params p = sp;
    const float* q = in + (size_t)i * 6;
    float o[3];
    brdf_one(p, q[0], q[1], q[2], q[3], q[4], q[5], o);
    out[(size_t)i * 3 + 0] = o[0];
    out[(size_t)i * 3 + 1] = o[1];
    out[(size_t)i * 3 + 2] = o[2];
}

extern "C" void kernel_launch(void* const* d_in, const int* in_sizes, int n_in,
                              void* d_out, int out_size) {
    const float* inputs = (const float*)d_in[0];
    int n = in_sizes[0] / 6;

    const float* a_bc  = (const float*)d_in[1];
    const float* a_mtl = (const float*)d_in[2];
    const float* a_sub = (const float*)d_in[3];
    const float* a_spec= (const float*)d_in[4];
    const float* a_rgh = (const float*)d_in[5];
    const float* a_spt = (const float*)d_in[6];
    const float* a_ani = (const float*)d_in[7];
    const float* a_shn = (const float*)d_in[8];
    const float* a_sht = (const float*)d_in[9];
    const float* a_cc  = (const float*)d_in[10];
    const float* a_ccg = (const float*)d_in[11];

    int nquad = n / 4;
    if (nquad > 0) {
        int threads = 128;
        int blocks = (nquad + threads - 1) / threads;
        brdf_kernel_vec<<<blocks, threads>>>((const float4*)inputs,
                                             (float4*)d_out, nquad,
                                             SCALAR_PASS);
    }
    int rem = n - nquad * 4;
    if (rem > 0) {
        brdf_kernel_tail<<<(rem + 127) / 128, 128>>>(inputs, (float*)d_out,
                                                     nquad * 4, n, SCALAR_PASS);
    }
}